// round 6
// baseline (speedup 1.0000x reference)
#include <cuda_runtime.h>
#include <cstdint>
#include <cstddef>

#define NB 4
#define NS 512
#define NH 8
#define NDH 64
#define NDM 512
#define NBH 32

// ---- scratch (device globals; no allocation) ----
__device__ float g_q [NBH * NS * NDH];
__device__ float g_k [NBH * NS * NDH];
__device__ float g_v [NBH * NDH * NS];   // transposed: [bh][d][s]
__device__ float g_qr[NBH * NS * NDH];   // pre-scaled by 0.125
__device__ float g_qb[NBH * NS];         // pre-scaled by 0.125
__device__ float g_s1[(size_t)NB * NS * NH * NS];  // scores [b][q][h][k], pre-scaled
__device__ float g_p [(size_t)NB * NS * NH * NS];  // probs  [b][q][h][k]

__device__ __forceinline__ uint32_t f2tf(float x) {
    uint32_t r; asm("cvt.rna.tf32.f32 %0, %1;" : "=r"(r) : "f"(x)); return r;
}
__device__ __forceinline__ void mma8(float* d, const uint32_t* a, const uint32_t* b) {
    asm volatile(
        "mma.sync.aligned.m16n8k8.row.col.f32.tf32.tf32.f32 "
        "{%0,%1,%2,%3}, {%4,%5,%6,%7}, {%8,%9}, {%0,%1,%2,%3};"
        : "+f"(d[0]), "+f"(d[1]), "+f"(d[2]), "+f"(d[3])
        : "r"(a[0]), "r"(a[1]), "r"(a[2]), "r"(a[3]), "r"(b[0]), "r"(b[1]));
}
__device__ __forceinline__ void cpa16(const void* smem_dst, const void* gmem_src) {
    uint32_t s = (uint32_t)__cvta_generic_to_shared(smem_dst);
    asm volatile("cp.async.cg.shared.global [%0], [%1], 16;" :: "r"(s), "l"(gmem_src));
}
#define CP_COMMIT() asm volatile("cp.async.commit_group;")
#define CP_WAIT3()  asm volatile("cp.async.wait_group 3;")
#define CP_WAIT2()  asm volatile("cp.async.wait_group 2;")
#define CP_WAIT1()  asm volatile("cp.async.wait_group 1;")
#define CP_WAIT0()  asm volatile("cp.async.wait_group 0;")

// ========= K1: q/k/v = X @ W^T (M=2048,N=512,K=512), 4-stage cp.async =======
#define K1_TILE 2304              // 64*36 floats per stage per operand
#define K1_SMEM (2 * 4 * K1_TILE * 4)

__global__ void __launch_bounds__(256) k_qkv(const float* __restrict__ X,
                                             const float* __restrict__ Wq,
                                             const float* __restrict__ Wk,
                                             const float* __restrict__ Wv) {
    extern __shared__ float dsm[];
    float* Xs = dsm;
    float* Ws = dsm + 4 * K1_TILE;
    const int z = blockIdx.z;
    const float* __restrict__ W = (z == 0) ? Wq : (z == 1) ? Wk : Wv;
    const int tid = threadIdx.x, lane = tid & 31, w = tid >> 5;
    const int g = lane >> 2, t = lane & 3, wm = w >> 2, wn = w & 3;
    const int m0 = blockIdx.x * 64, n0 = blockIdx.y * 64;
    const int lr = tid >> 3, lc = (tid & 7) * 4;
    float acc[2][2][4] = {};

    auto issue = [&](int ki) {
        int bi = (ki & 3) * K1_TILE, kt = ki * 32;
#pragma unroll
        for (int rr = 0; rr < 2; rr++) {
            int r = lr + rr * 32;
            cpa16(&Xs[bi + r * 36 + lc], &X[(size_t)(m0 + r) * NDM + kt + lc]);
            cpa16(&Ws[bi + r * 36 + lc], &W[(size_t)(n0 + r) * NDM + kt + lc]);
        }
    };
    issue(0); CP_COMMIT(); issue(1); CP_COMMIT(); issue(2); CP_COMMIT();
    for (int ki = 0; ki < 16; ki++) {
        if (ki <= 13) CP_WAIT2(); else if (ki == 14) CP_WAIT1(); else CP_WAIT0();
        __syncthreads();
        if (ki < 13) { issue(ki + 3); CP_COMMIT(); }
        const float* Xf = Xs + (ki & 3) * K1_TILE;
        const float* Wf = Ws + (ki & 3) * K1_TILE;
#pragma unroll
        for (int ks = 0; ks < 4; ks++) {
            uint32_t a[2][4], bb[2][2];
#pragma unroll
            for (int mi = 0; mi < 2; mi++) {
                int r = wm * 32 + mi * 16 + g;
                a[mi][0] = f2tf(Xf[r*36 + ks*8 + t]);     a[mi][1] = f2tf(Xf[(r+8)*36 + ks*8 + t]);
                a[mi][2] = f2tf(Xf[r*36 + ks*8 + t + 4]); a[mi][3] = f2tf(Xf[(r+8)*36 + ks*8 + t + 4]);
            }
#pragma unroll
            for (int ni = 0; ni < 2; ni++) {
                int c = wn * 16 + ni * 8 + g;
                bb[ni][0] = f2tf(Wf[c*36 + ks*8 + t]); bb[ni][1] = f2tf(Wf[c*36 + ks*8 + t + 4]);
            }
#pragma unroll
            for (int mi = 0; mi < 2; mi++)
#pragma unroll
                for (int ni = 0; ni < 2; ni++) mma8(acc[mi][ni], a[mi], bb[ni]);
        }
        __syncthreads();
    }
#pragma unroll
    for (int mi = 0; mi < 2; mi++)
#pragma unroll
        for (int ni = 0; ni < 2; ni++) {
            int m = m0 + wm*32 + mi*16 + g, n = n0 + wn*16 + ni*8 + 2*t;
            int b = m >> 9, s = m & 511, h = n >> 6, d = n & 63, bh = b*NH + h;
            if (z == 2) {
                g_v[(bh*NDH + d)  *NS + s]     = acc[mi][ni][0];
                g_v[(bh*NDH + d+1)*NS + s]     = acc[mi][ni][1];
                g_v[(bh*NDH + d)  *NS + s + 8] = acc[mi][ni][2];
                g_v[(bh*NDH + d+1)*NS + s + 8] = acc[mi][ni][3];
            } else {
                float* o = (z == 0) ? g_q : g_k;
                float* o1 = &o[((bh*NS + s)    *NDH) + d];
                float* o2 = &o[((bh*NS + s + 8)*NDH) + d];
                o1[0]=acc[mi][ni][0]; o1[1]=acc[mi][ni][1];
                o2[0]=acc[mi][ni][2]; o2[1]=acc[mi][ni][3];
            }
        }
}

// ================= K2: qr = 0.125*(q@Wr) ; qb = 0.125*(q.br) ================
__global__ void __launch_bounds__(256) k_qr(const float* __restrict__ Wr,
                                            const float* __restrict__ br) {
    __shared__ float Wrs[64 * 64], qs[8][64], brs[64];
    const int tid = threadIdx.x;
    for (int i = tid; i < 64 * 64; i += 256) Wrs[i] = Wr[i];
    if (tid < 64) brs[tid] = br[tid];
    const int w = tid >> 5, lane = tid & 31;
    const int row = blockIdx.x * 8 + w;
    const float* qrow = &g_q[(size_t)row * NDH];
    float q0 = qrow[lane], q1 = qrow[lane + 32];
    qs[w][lane] = q0; qs[w][lane + 32] = q1;
    __syncthreads();
    float a0 = 0.f, a1 = 0.f;
#pragma unroll
    for (int d = 0; d < 64; d++) {
        float qd = qs[w][d];
        a0 += qd * Wrs[d * 64 + lane];
        a1 += qd * Wrs[d * 64 + lane + 32];
    }
    g_qr[row * NDH + lane] = a0 * 0.125f;
    g_qr[row * NDH + lane + 32] = a1 * 0.125f;
    float pb = q0 * brs[lane] + q1 * brs[lane + 32];
#pragma unroll
    for (int o = 16; o; o >>= 1) pb += __shfl_xor_sync(0xffffffffu, pb, o);
    if (lane == 0) g_qb[row] = pb * 0.125f;
}

// ======= K3: 0.125*q k^T per (b,h), scores -> [b][q][h][k]; 2 K-half groups =
__global__ void __launch_bounds__(256) k_qk() {
    const int bh = blockIdx.z, b = bh >> 3, h = bh & 7;
    const float* __restrict__ Q = &g_q[(size_t)bh * NS * NDH];
    const float* __restrict__ K = &g_k[(size_t)bh * NS * NDH];
    __shared__ float As[64 * 68], Bs[64 * 68];
    const int tid = threadIdx.x, lane = tid & 31, w = tid >> 5;
    const int g = lane >> 2, t = lane & 3, wm = w >> 2, wn = w & 3;
    const int m0 = blockIdx.x * 64, n0 = blockIdx.y * 64;
    const int c4 = (tid & 15) * 4, r0 = tid >> 4;
    if (c4 < 32) {
#pragma unroll
        for (int rr = 0; rr < 4; rr++) {
            int r = r0 + rr * 16;
            cpa16(&As[r * 68 + c4], &Q[(m0 + r) * NDH + c4]);
            cpa16(&Bs[r * 68 + c4], &K[(n0 + r) * NDH + c4]);
        }
    }
    CP_COMMIT();
    if (c4 >= 32) {
#pragma unroll
        for (int rr = 0; rr < 4; rr++) {
            int r = r0 + rr * 16;
            cpa16(&As[r * 68 + c4], &Q[(m0 + r) * NDH + c4]);
            cpa16(&Bs[r * 68 + c4], &K[(n0 + r) * NDH + c4]);
        }
    }
    CP_COMMIT();
    float acc[2][2][4] = {};
    for (int half = 0; half < 2; half++) {
        if (half == 0) CP_WAIT1(); else CP_WAIT0();
        __syncthreads();
#pragma unroll
        for (int ks4 = 0; ks4 < 4; ks4++) {
            int ks = half * 4 + ks4;
            uint32_t a[2][4], bb[2][2];
#pragma unroll
            for (int mi = 0; mi < 2; mi++) {
                int r = wm * 32 + mi * 16 + g;
                a[mi][0] = f2tf(As[r*68 + ks*8 + t]);     a[mi][1] = f2tf(As[(r+8)*68 + ks*8 + t]);
                a[mi][2] = f2tf(As[r*68 + ks*8 + t + 4]); a[mi][3] = f2tf(As[(r+8)*68 + ks*8 + t + 4]);
            }
#pragma unroll
            for (int ni = 0; ni < 2; ni++) {
                int c = wn * 16 + ni * 8 + g;
                bb[ni][0] = f2tf(Bs[c*68 + ks*8 + t]); bb[ni][1] = f2tf(Bs[c*68 + ks*8 + t + 4]);
            }
#pragma unroll
            for (int mi = 0; mi < 2; mi++)
#pragma unroll
                for (int ni = 0; ni < 2; ni++) mma8(acc[mi][ni], a[mi], bb[ni]);
        }
    }
#pragma unroll
    for (int mi = 0; mi < 2; mi++)
#pragma unroll
        for (int ni = 0; ni < 2; ni++) {
            int m = m0 + wm*32 + mi*16 + g, n = n0 + wn*16 + ni*8 + 2*t;
            float* o1 = &g_s1[((size_t)(b*NS + m)    *NH + h)*NS + n];
            float* o2 = &g_s1[((size_t)(b*NS + m + 8)*NH + h)*NS + n];
            o1[0] = acc[mi][ni][0] * 0.125f; o1[1] = acc[mi][ni][1] * 0.125f;
            o2[0] = acc[mi][ni][2] * 0.125f; o2[1] = acc[mi][ni][3] * 0.125f;
        }
}

// ===== K4: per (b,q): rel mma + scores + mask + softmax. 128 thr, 8x64 chunks
#define RELW64 (64 * 68)
#define OFF_SC (4 * RELW64)          // 17408
#define OFF_GR (OFF_SC + 4096)       // 21504
#define OFF_QR (OFF_GR + 512)        // 22016
#define OFF_QB (OFF_QR + 8 * 68)     // 22560
#define OFF_RED (OFF_QB + 8)         // 22568
#define K4_SMEM ((OFF_RED + 64) * 4) // 90528 bytes

__global__ void __launch_bounds__(128) k_relsm(const float* __restrict__ REL,
                                               const int* __restrict__ GRAPH) {
    extern __shared__ float sm[];
    float* relb = sm;
    float* sc_s = sm + OFF_SC;
    const int* gr_i = (const int*)(sm + OFF_GR);
    uint32_t* qrs = (uint32_t*)(sm + OFF_QR);
    float* qbs = sm + OFF_QB;
    float* red = sm + OFF_RED;   // [2][4 warps][8 h]

    const int q = blockIdx.x, b = blockIdx.y;
    const int tid = threadIdx.x, lane = tid & 31, w = tid >> 5;   // w in 0..3
    const int g = lane >> 2, t = lane & 3;

    const float* relrow = REL + (size_t)(b*NS + q) * NS * NDH;
    const float* scrow  = &g_s1[(size_t)(b*NS + q) * NH * NS];
    const int*   grow   = &GRAPH[(size_t)(b*NS + q) * NS];

    auto issue_rel = [&](int ch) {
        const float* src = relrow + (size_t)ch * 64 * NDH;
        float* dst = relb + (ch & 3) * RELW64;
        int c4 = (tid & 15) * 4, r0 = tid >> 4;
#pragma unroll
        for (int rr = 0; rr < 8; rr++) {
            int r = r0 + rr * 8;
            cpa16(&dst[r * 68 + c4], src + (size_t)r * NDH + c4);
        }
    };
    // group A: scores (16KB) + graph (2KB) + rel chunk 0
    {
        int c4 = tid * 4;
#pragma unroll
        for (int i = 0; i < 8; i++) cpa16(&sc_s[c4 + i * 512], scrow + c4 + i * 512);
        cpa16((float*)gr_i + c4, grow + c4);
    }
    issue_rel(0); CP_COMMIT();
    issue_rel(1); CP_COMMIT();
    issue_rel(2); CP_COMMIT();

    // stage qr fragments + qb (plain loads)
    if (tid < 8) qbs[tid] = g_qb[(b*NH + tid)*NS + q];
    for (int i = tid; i < 512; i += 128) {
        int h = i >> 6, r = i & 63;
        qrs[h * 68 + r] = f2tf(g_qr[(size_t)((b*NH + h)*NS + q) * NDH + r]);
    }
    __syncthreads();
    uint32_t bf[8][2];
#pragma unroll
    for (int ks = 0; ks < 8; ks++) {
        bf[ks][0] = qrs[g*68 + ks*8 + t];
        bf[ks][1] = qrs[g*68 + ks*8 + t + 4];
    }

    float sc[32];
    for (int ch = 0; ch < 8; ch++) {
        if (ch <= 5) CP_WAIT2(); else if (ch == 6) CP_WAIT1(); else CP_WAIT0();
        __syncthreads();
        if (ch < 5) { issue_rel(ch + 3); CP_COMMIT(); }
        const float* buf = relb + (ch & 3) * RELW64;
        float c[4] = {0,0,0,0};
        int r0 = w * 16 + g;
#pragma unroll
        for (int ks = 0; ks < 8; ks++) {
            uint32_t a[4];
            a[0] = f2tf(buf[r0*68 + ks*8 + t]);     a[1] = f2tf(buf[(r0+8)*68 + ks*8 + t]);
            a[2] = f2tf(buf[r0*68 + ks*8 + t + 4]); a[3] = f2tf(buf[(r0+8)*68 + ks*8 + t + 4]);
            mma8(c, a, bf[ks]);
        }
        int k0 = ch * 64 + w * 16;
#pragma unroll
        for (int j = 0; j < 4; j++) {
            int k = k0 + g + ((j >= 2) ? 8 : 0);
            int h = 2 * t + (j & 1);
            float s = sc_s[h * NS + k] + c[j] + qbs[h];
            s += (1.f - (float)gr_i[k]) * -1e9f;
            sc[ch * 4 + j] = s;
        }
    }
    // softmax: even sc index -> h=2t, odd -> h=2t+1
    float mx0 = -3e38f, mx1 = -3e38f;
#pragma unroll
    for (int i = 0; i < 32; i++) { if (i & 1) mx1 = fmaxf(mx1, sc[i]); else mx0 = fmaxf(mx0, sc[i]); }
#pragma unroll
    for (int o = 4; o < 32; o <<= 1) {
        mx0 = fmaxf(mx0, __shfl_xor_sync(0xffffffffu, mx0, o));
        mx1 = fmaxf(mx1, __shfl_xor_sync(0xffffffffu, mx1, o));
    }
    if (g == 0) { red[w*8 + 2*t] = mx0; red[w*8 + 2*t+1] = mx1; }
    __syncthreads();
    float fm0 = -3e38f, fm1 = -3e38f;
#pragma unroll
    for (int ww = 0; ww < 4; ww++) {
        fm0 = fmaxf(fm0, red[ww*8 + 2*t]); fm1 = fmaxf(fm1, red[ww*8 + 2*t+1]);
    }
    float s0 = 0.f, s1 = 0.f;
#pragma unroll
    for (int i = 0; i < 32; i++) {
        float e = __expf(sc[i] - ((i & 1) ? fm1 : fm0));
        sc[i] = e;
        if (i & 1) s1 += e; else s0 += e;
    }
#pragma unroll
    for (int o = 4; o < 32; o <<= 1) {
        s0 += __shfl_xor_sync(0xffffffffu, s0, o);
        s1 += __shfl_xor_sync(0xffffffffu, s1, o);
    }
    if (g == 0) { red[32 + w*8 + 2*t] = s0; red[32 + w*8 + 2*t+1] = s1; }
    __syncthreads();
    float ts0 = 0.f, ts1 = 0.f;
#pragma unroll
    for (int ww = 0; ww < 4; ww++) { ts0 += red[32 + ww*8 + 2*t]; ts1 += red[32 + ww*8 + 2*t+1]; }
    float r0i = 1.f / ts0, r1i = 1.f / ts1;

    // stage probs into sc_s [h][k], then contiguous float4 store
#pragma unroll
    for (int ch = 0; ch < 8; ch++) {
        int k0 = ch * 64 + w * 16;
#pragma unroll
        for (int j = 0; j < 4; j++) {
            int k = k0 + g + ((j >= 2) ? 8 : 0);
            int h = 2 * t + (j & 1);
            sc_s[h * NS + k] = sc[ch*4+j] * ((j & 1) ? r1i : r0i);
        }
    }
    __syncthreads();
    float* pout = &g_p[(size_t)(b*NS + q) * NH * NS];
    for (int i = tid; i < 1024; i += 128)
        *(float4*)&pout[i * 4] = *(const float4*)&sc_s[i * 4];
}

// ========= K5: out = probs @ v per (b,h), 4-stage cp.async =================
#define K5_TILE 2304
#define K5_SMEM (2 * 4 * K5_TILE * 4)

__global__ void __launch_bounds__(256) k_pv(float* __restrict__ OUT) {
    extern __shared__ float dsm[];
    float* As = dsm;
    float* Bs = dsm + 4 * K5_TILE;
    const int bh = blockIdx.z, b = bh >> 3, h = bh & 7;
    const float* __restrict__ VT = &g_v[(size_t)bh * NDH * NS];
    const int tid = threadIdx.x, lane = tid & 31, w = tid >> 5;
    const int g = lane >> 2, t = lane & 3, wm = w >> 2, wn = w & 3;
    const int m0 = blockIdx.x * 64;
    const int lr = tid >> 3, lc = (tid & 7) * 4;
    float acc[2][2][4] = {};

    auto issue = [&](int ki) {
        int bi = (ki & 3) * K5_TILE, kt = ki * 32;
#pragma unroll
        for (int rr = 0; rr < 2; rr++) {
            int r = lr + rr * 32;
            cpa16(&As[bi + r * 36 + lc], &g_p[((size_t)(b*NS + m0 + r)*NH + h)*NS + kt + lc]);
            cpa16(&Bs[bi + r * 36 + lc], &VT[(size_t)r * NS + kt + lc]);
        }
    };
    issue(0); CP_COMMIT(); issue(1); CP_COMMIT(); issue(2); CP_COMMIT();
    for (int ki = 0; ki < 16; ki++) {
        if (ki <= 13) CP_WAIT2(); else if (ki == 14) CP_WAIT1(); else CP_WAIT0();
        __syncthreads();
        if (ki < 13) { issue(ki + 3); CP_COMMIT(); }
        const float* Af = As + (ki & 3) * K5_TILE;
        const float* Bf = Bs + (ki & 3) * K5_TILE;
#pragma unroll
        for (int ks = 0; ks < 4; ks++) {
            uint32_t a[2][4], bb[2][2];
#pragma unroll
            for (int mi = 0; mi < 2; mi++) {
                int r = wm * 32 + mi * 16 + g;
                a[mi][0] = f2tf(Af[r*36 + ks*8 + t]);     a[mi][1] = f2tf(Af[(r+8)*36 + ks*8 + t]);
                a[mi][2] = f2tf(Af[r*36 + ks*8 + t + 4]); a[mi][3] = f2tf(Af[(r+8)*36 + ks*8 + t + 4]);
            }
#pragma unroll
            for (int ni = 0; ni < 2; ni++) {
                int c = wn * 16 + ni * 8 + g;
                bb[ni][0] = f2tf(Bf[c*36 + ks*8 + t]); bb[ni][1] = f2tf(Bf[c*36 + ks*8 + t + 4]);
            }
#pragma unroll
            for (int mi = 0; mi < 2; mi++)
#pragma unroll
                for (int ni = 0; ni < 2; ni++) mma8(acc[mi][ni], a[mi], bb[ni]);
        }
        __syncthreads();
    }
#pragma unroll
    for (int mi = 0; mi < 2; mi++)
#pragma unroll
        for (int ni = 0; ni < 2; ni++) {
            int m = m0 + wm*32 + mi*16 + g, n = wn*16 + ni*8 + 2*t;
            float* o1 = &OUT[(size_t)(b*NS + m)    *NDM + h*NDH + n];
            float* o2 = &OUT[(size_t)(b*NS + m + 8)*NDM + h*NDH + n];
            o1[0]=acc[mi][ni][0]; o1[1]=acc[mi][ni][1];
            o2[0]=acc[mi][ni][2]; o2[1]=acc[mi][ni][3];
        }
}

extern "C" void kernel_launch(void* const* d_in, const int* in_sizes, int n_in,
                              void* d_out, int out_size) {
    const float* X     = (const float*)d_in[0];
    const int*   GRAPH = (const int*)  d_in[1];
    const float* REL   = (const float*)d_in[2];
    const float* Wq    = (const float*)d_in[3];
    const float* Wk    = (const float*)d_in[4];
    const float* Wv    = (const float*)d_in[5];
    const float* Wr    = (const float*)d_in[6];
    const float* br    = (const float*)d_in[7];
    float* OUT = (float*)d_out;

    static bool attr_set = false;
    if (!attr_set) {
        cudaFuncSetAttribute(k_qkv,   cudaFuncAttributeMaxDynamicSharedMemorySize, K1_SMEM);
        cudaFuncSetAttribute(k_relsm, cudaFuncAttributeMaxDynamicSharedMemorySize, K4_SMEM);
        cudaFuncSetAttribute(k_pv,    cudaFuncAttributeMaxDynamicSharedMemorySize, K5_SMEM);
        attr_set = true;
    }

    k_qkv  <<<dim3(32, 8, 3), 256, K1_SMEM>>>(X, Wq, Wk, Wv);
    k_qr   <<<2048, 256>>>(Wr, br);
    k_qk   <<<dim3(8, 8, 32), 256>>>();
    k_relsm<<<dim3(512, 4), 128, K4_SMEM>>>(REL, GRAPH);
    k_pv   <<<dim3(8, 1, 32), 256, K5_SMEM>>>(OUT);
}

// round 7
// speedup vs baseline: 1.2234x; 1.2234x over previous
#include <cuda_runtime.h>
#include <cstdint>
#include <cstddef>

#define NB 4
#define NS 512
#define NH 8
#define NDH 64
#define NDM 512
#define NBH 32

// ---- scratch (device globals; no allocation) ----
__device__ float g_q [NBH * NS * NDH];
__device__ float g_k [NBH * NS * NDH];
__device__ float g_v [NBH * NDH * NS];   // transposed: [bh][d][s]
__device__ float g_qr[NBH * NS * NDH];   // pre-scaled by 0.125
__device__ float g_qb[NBH * NS];         // pre-scaled by 0.125
__device__ float g_s1[(size_t)NB * NS * NH * NS];  // scores [b][q][h][k], pre-scaled
__device__ float g_p [(size_t)NB * NS * NH * NS];  // probs  [b][q][h][k]

__device__ __forceinline__ uint32_t f2tf(float x) {
    uint32_t r; asm("cvt.rna.tf32.f32 %0, %1;" : "=r"(r) : "f"(x)); return r;
}
__device__ __forceinline__ void mma8(float* d, const uint32_t* a, const uint32_t* b) {
    asm volatile(
        "mma.sync.aligned.m16n8k8.row.col.f32.tf32.tf32.f32 "
        "{%0,%1,%2,%3}, {%4,%5,%6,%7}, {%8,%9}, {%0,%1,%2,%3};"
        : "+f"(d[0]), "+f"(d[1]), "+f"(d[2]), "+f"(d[3])
        : "r"(a[0]), "r"(a[1]), "r"(a[2]), "r"(a[3]), "r"(b[0]), "r"(b[1]));
}
__device__ __forceinline__ void cpa16(const void* smem_dst, const void* gmem_src) {
    uint32_t s = (uint32_t)__cvta_generic_to_shared(smem_dst);
    asm volatile("cp.async.cg.shared.global [%0], [%1], 16;" :: "r"(s), "l"(gmem_src));
}
#define CP_COMMIT() asm volatile("cp.async.commit_group;")
#define CP_WAIT1()  asm volatile("cp.async.wait_group 1;")
#define CP_WAIT0()  asm volatile("cp.async.wait_group 0;")

// ========= K1: q/k/v = X @ W^T (2048x512x512), 2-stage, single-sync,
//           z==0 additionally computes qr = 0.125*q@Wr and qb = 0.125*q.br ===
// dyn smem floats: stages [0,9216) = Xs0|Xs1|Ws0|Ws1 (2304 each)
//                  epilogue reuse: Qs = [0,4352), WrT = [4608,8960), brs = [9216,9280)
#define K1_SMEM (9280 * 4)

__global__ void __launch_bounds__(256) k_qkv(const float* __restrict__ X,
                                             const float* __restrict__ Wq,
                                             const float* __restrict__ Wk,
                                             const float* __restrict__ Wv,
                                             const float* __restrict__ Wr,
                                             const float* __restrict__ br) {
    extern __shared__ float dsm[];
    const int z = blockIdx.z;
    const float* __restrict__ W = (z == 0) ? Wq : (z == 1) ? Wk : Wv;
    const int tid = threadIdx.x, lane = tid & 31, w = tid >> 5;
    const int g = lane >> 2, t = lane & 3, wm = w >> 2, wn = w & 3;
    const int m0 = blockIdx.x * 64, n0 = blockIdx.y * 64;
    const int lr = tid >> 3, lc = (tid & 7) * 4;
    float acc[2][2][4] = {};

    auto issue = [&](int ki) {
        float* Xs = dsm + (ki & 1) * 2304;
        float* Ws = dsm + 4608 + (ki & 1) * 2304;
        int kt = ki * 32;
#pragma unroll
        for (int rr = 0; rr < 2; rr++) {
            int r = lr + rr * 32;
            cpa16(&Xs[r * 36 + lc], &X[(size_t)(m0 + r) * NDM + kt + lc]);
            cpa16(&Ws[r * 36 + lc], &W[(size_t)(n0 + r) * NDM + kt + lc]);
        }
    };
    issue(0); CP_COMMIT();
    for (int ki = 0; ki < 16; ki++) {
        CP_WAIT0();
        __syncthreads();
        if (ki < 15) { issue(ki + 1); CP_COMMIT(); }
        const float* Xf = dsm + (ki & 1) * 2304;
        const float* Wf = dsm + 4608 + (ki & 1) * 2304;
#pragma unroll
        for (int ks = 0; ks < 4; ks++) {
            uint32_t a[2][4], bb[2][2];
#pragma unroll
            for (int mi = 0; mi < 2; mi++) {
                int r = wm * 32 + mi * 16 + g;
                a[mi][0] = f2tf(Xf[r*36 + ks*8 + t]);     a[mi][1] = f2tf(Xf[(r+8)*36 + ks*8 + t]);
                a[mi][2] = f2tf(Xf[r*36 + ks*8 + t + 4]); a[mi][3] = f2tf(Xf[(r+8)*36 + ks*8 + t + 4]);
            }
#pragma unroll
            for (int ni = 0; ni < 2; ni++) {
                int c = wn * 16 + ni * 8 + g;
                bb[ni][0] = f2tf(Wf[c*36 + ks*8 + t]); bb[ni][1] = f2tf(Wf[c*36 + ks*8 + t + 4]);
            }
#pragma unroll
            for (int mi = 0; mi < 2; mi++)
#pragma unroll
                for (int ni = 0; ni < 2; ni++) mma8(acc[mi][ni], a[mi], bb[ni]);
        }
    }
    // global store of q/k/v
#pragma unroll
    for (int mi = 0; mi < 2; mi++)
#pragma unroll
        for (int ni = 0; ni < 2; ni++) {
            int m = m0 + wm*32 + mi*16 + g, n = n0 + wn*16 + ni*8 + 2*t;
            int b = m >> 9, s = m & 511, h = n >> 6, d = n & 63, bh = b*NH + h;
            if (z == 2) {
                g_v[(bh*NDH + d)  *NS + s]     = acc[mi][ni][0];
                g_v[(bh*NDH + d+1)*NS + s]     = acc[mi][ni][1];
                g_v[(bh*NDH + d)  *NS + s + 8] = acc[mi][ni][2];
                g_v[(bh*NDH + d+1)*NS + s + 8] = acc[mi][ni][3];
            } else {
                float* o = (z == 0) ? g_q : g_k;
                float* o1 = &o[((bh*NS + s)    *NDH) + d];
                float* o2 = &o[((bh*NS + s + 8)*NDH) + d];
                o1[0]=acc[mi][ni][0]; o1[1]=acc[mi][ni][1];
                o2[0]=acc[mi][ni][2]; o2[1]=acc[mi][ni][3];
            }
        }
    if (z != 0) return;

    // ---- fused qr/qb epilogue (this CTA holds q[m0..m0+63][head hB][0..63]) --
    float* Qs  = dsm;            // [64][68]
    float* WrT = dsm + 4608;     // [64 r][68 d]: WrT[r][d] = Wr[d][r]
    float* brs = dsm + 9216;
    const int hB = blockIdx.y;
    __syncthreads();   // everyone done reading stage buffers
#pragma unroll
    for (int mi = 0; mi < 2; mi++)
#pragma unroll
        for (int ni = 0; ni < 2; ni++) {
            int ml = wm*32 + mi*16 + g, nl = wn*16 + ni*8 + 2*t;
            Qs[ml*68 + nl] = acc[mi][ni][0];     Qs[ml*68 + nl + 1] = acc[mi][ni][1];
            Qs[(ml+8)*68 + nl] = acc[mi][ni][2]; Qs[(ml+8)*68 + nl + 1] = acc[mi][ni][3];
        }
    for (int i = tid; i < 4096; i += 256) {
        int d = i >> 6, r = i & 63;
        WrT[r*68 + d] = Wr[i];     // coalesced read
    }
    if (tid < 64) brs[tid] = br[tid];
    __syncthreads();

    float qacc[2][2][4] = {};
#pragma unroll
    for (int ks = 0; ks < 8; ks++) {
        uint32_t a[2][4], bb[2][2];
#pragma unroll
        for (int mi = 0; mi < 2; mi++) {
            int r = wm * 32 + mi * 16 + g;
            a[mi][0] = f2tf(Qs[r*68 + ks*8 + t]);     a[mi][1] = f2tf(Qs[(r+8)*68 + ks*8 + t]);
            a[mi][2] = f2tf(Qs[r*68 + ks*8 + t + 4]); a[mi][3] = f2tf(Qs[(r+8)*68 + ks*8 + t + 4]);
        }
#pragma unroll
        for (int ni = 0; ni < 2; ni++) {
            int c = wn * 16 + ni * 8 + g;
            bb[ni][0] = f2tf(WrT[c*68 + ks*8 + t]); bb[ni][1] = f2tf(WrT[c*68 + ks*8 + t + 4]);
        }
#pragma unroll
        for (int mi = 0; mi < 2; mi++)
#pragma unroll
            for (int ni = 0; ni < 2; ni++) mma8(qacc[mi][ni], a[mi], bb[ni]);
    }
#pragma unroll
    for (int mi = 0; mi < 2; mi++)
#pragma unroll
        for (int ni = 0; ni < 2; ni++) {
            int ml = wm*32 + mi*16 + g, col = wn*16 + ni*8 + 2*t;
            int m = m0 + ml, b = m >> 9, s = m & 511;
            float* o1 = &g_qr[(((size_t)(b*NH + hB)*NS + s)     ) * NDH + col];
            float* o2 = &g_qr[(((size_t)(b*NH + hB)*NS + (s+8)) ) * NDH + col];
            o1[0] = qacc[mi][ni][0] * 0.125f; o1[1] = qacc[mi][ni][1] * 0.125f;
            o2[0] = qacc[mi][ni][2] * 0.125f; o2[1] = qacc[mi][ni][3] * 0.125f;
        }
    // qb: 4 threads per row
    {
        int row = tid >> 2, qg = tid & 3;
        float p = 0.f;
#pragma unroll
        for (int d = 0; d < 16; d++) p += Qs[row*68 + qg*16 + d] * brs[qg*16 + d];
        p += __shfl_xor_sync(0xffffffffu, p, 1);
        p += __shfl_xor_sync(0xffffffffu, p, 2);
        if (qg == 0) {
            int m = m0 + row, b = m >> 9, s = m & 511;
            g_qb[(b*NH + hB)*NS + s] = p * 0.125f;
        }
    }
}

// ======= K3: 0.125*q k^T per (b,h), scores -> [b][q][h][k] ==================
__global__ void __launch_bounds__(256) k_qk() {
    const int bh = blockIdx.z, b = bh >> 3, h = bh & 7;
    const float* __restrict__ Q = &g_q[(size_t)bh * NS * NDH];
    const float* __restrict__ K = &g_k[(size_t)bh * NS * NDH];
    __shared__ float As[64 * 68], Bs[64 * 68];
    const int tid = threadIdx.x, lane = tid & 31, w = tid >> 5;
    const int g = lane >> 2, t = lane & 3, wm = w >> 2, wn = w & 3;
    const int m0 = blockIdx.x * 64, n0 = blockIdx.y * 64;
#pragma unroll
    for (int rr = 0; rr < 4; rr++) {
        int r = (tid >> 4) + rr * 16, c4 = (tid & 15) * 4;
        cpa16(&As[r * 68 + c4], &Q[(m0 + r) * NDH + c4]);
        cpa16(&Bs[r * 68 + c4], &K[(n0 + r) * NDH + c4]);
    }
    CP_COMMIT(); CP_WAIT0();
    __syncthreads();
    float acc[2][2][4] = {};
#pragma unroll
    for (int ks = 0; ks < 8; ks++) {
        uint32_t a[2][4], bb[2][2];
#pragma unroll
        for (int mi = 0; mi < 2; mi++) {
            int r = wm * 32 + mi * 16 + g;
            a[mi][0] = f2tf(As[r*68 + ks*8 + t]);     a[mi][1] = f2tf(As[(r+8)*68 + ks*8 + t]);
            a[mi][2] = f2tf(As[r*68 + ks*8 + t + 4]); a[mi][3] = f2tf(As[(r+8)*68 + ks*8 + t + 4]);
        }
#pragma unroll
        for (int ni = 0; ni < 2; ni++) {
            int c = wn * 16 + ni * 8 + g;
            bb[ni][0] = f2tf(Bs[c*68 + ks*8 + t]); bb[ni][1] = f2tf(Bs[c*68 + ks*8 + t + 4]);
        }
#pragma unroll
        for (int mi = 0; mi < 2; mi++)
#pragma unroll
            for (int ni = 0; ni < 2; ni++) mma8(acc[mi][ni], a[mi], bb[ni]);
    }
#pragma unroll
    for (int mi = 0; mi < 2; mi++)
#pragma unroll
        for (int ni = 0; ni < 2; ni++) {
            int m = m0 + wm*32 + mi*16 + g, n = n0 + wn*16 + ni*8 + 2*t;
            float* o1 = &g_s1[((size_t)(b*NS + m)    *NH + h)*NS + n];
            float* o2 = &g_s1[((size_t)(b*NS + m + 8)*NH + h)*NS + n];
            o1[0] = acc[mi][ni][0] * 0.125f; o1[1] = acc[mi][ni][1] * 0.125f;
            o2[0] = acc[mi][ni][2] * 0.125f; o2[1] = acc[mi][ni][3] * 0.125f;
        }
}

// ===== K4: per (b,q): rel mma + scores(reg) + mask + softmax ================
// dyn smem floats: relb[2][128*68] | qrs[8*68] | qbs[8] | red[128]
#define RELW   (128 * 68)
#define OFF_QR (2 * RELW)
#define OFF_QB (OFF_QR + 8 * 68)
#define OFF_RED (OFF_QB + 8)
#define K4_SMEM ((OFF_RED + 128) * 4)   // 72,992 bytes -> 3 CTAs/SM

__global__ void __launch_bounds__(256) k_relsm(const float* __restrict__ REL,
                                               const int* __restrict__ GRAPH) {
    extern __shared__ float sm[];
    float* relb = sm;
    uint32_t* qrs = (uint32_t*)(sm + OFF_QR);
    float* qbs = sm + OFF_QB;
    float* red = sm + OFF_RED;   // [2][8 warps][8 h]

    const int q = blockIdx.x, b = blockIdx.y;
    const int tid = threadIdx.x, lane = tid & 31, w = tid >> 5;
    const int g = lane >> 2, t = lane & 3;

    const float* relrow = REL + (size_t)(b*NS + q) * NS * NDH;
    const float* scrow  = &g_s1[(size_t)(b*NS + q) * NH * NS];
    const int*   grow   = &GRAPH[(size_t)(b*NS + q) * NS];

    auto issue_rel = [&](int ch) {
        const float* src = relrow + (size_t)ch * 128 * NDH;
        float* dst = relb + (ch & 1) * RELW;
        int c4 = (tid & 15) * 4, r0 = tid >> 4;
#pragma unroll
        for (int rr = 0; rr < 8; rr++) {
            int r = r0 + rr * 16;
            cpa16(&dst[r * 68 + c4], src + (size_t)r * NDH + c4);
        }
    };
    issue_rel(0); CP_COMMIT();
    issue_rel(1); CP_COMMIT();

    // scores + graph -> registers (masked at load)
    float sc[16];
#pragma unroll
    for (int ch = 0; ch < 4; ch++) {
        int k0 = ch * 128 + w * 16;
#pragma unroll
        for (int j = 0; j < 4; j++) {
            int k = k0 + g + ((j >= 2) ? 8 : 0);
            int h = 2 * t + (j & 1);
            sc[ch*4+j] = scrow[(size_t)h*NS + k] + (1.f - (float)grow[k]) * -1e9f;
        }
    }
    if (tid < 8) qbs[tid] = g_qb[(b*NH + tid)*NS + q];
    for (int i = tid; i < 512; i += 256) {
        int h = i >> 6, r = i & 63;
        qrs[h * 68 + r] = f2tf(g_qr[(size_t)((b*NH + h)*NS + q) * NDH + r]);
    }
    __syncthreads();
    uint32_t bf[8][2];
#pragma unroll
    for (int ks = 0; ks < 8; ks++) {
        bf[ks][0] = qrs[g*68 + ks*8 + t];
        bf[ks][1] = qrs[g*68 + ks*8 + t + 4];
    }
    const float qb0 = qbs[2*t], qb1 = qbs[2*t + 1];

    for (int ch = 0; ch < 4; ch++) {
        if (ch < 3) CP_WAIT1(); else CP_WAIT0();
        __syncthreads();
        const float* buf = relb + (ch & 1) * RELW;
        float c[4] = {0,0,0,0};
        int r0 = w * 16 + g;
#pragma unroll
        for (int ks = 0; ks < 8; ks++) {
            uint32_t a[4];
            a[0] = f2tf(buf[r0*68 + ks*8 + t]);     a[1] = f2tf(buf[(r0+8)*68 + ks*8 + t]);
            a[2] = f2tf(buf[r0*68 + ks*8 + t + 4]); a[3] = f2tf(buf[(r0+8)*68 + ks*8 + t + 4]);
            mma8(c, a, bf[ks]);
        }
#pragma unroll
        for (int j = 0; j < 4; j++)
            sc[ch*4+j] += c[j] + ((j & 1) ? qb1 : qb0);
        __syncthreads();
        if (ch < 2) { issue_rel(ch + 2); CP_COMMIT(); }
    }
    // softmax: even sc index -> h=2t, odd -> h=2t+1
    float mx0 = -3e38f, mx1 = -3e38f;
#pragma unroll
    for (int i = 0; i < 16; i++) { if (i & 1) mx1 = fmaxf(mx1, sc[i]); else mx0 = fmaxf(mx0, sc[i]); }
#pragma unroll
    for (int o = 4; o < 32; o <<= 1) {
        mx0 = fmaxf(mx0, __shfl_xor_sync(0xffffffffu, mx0, o));
        mx1 = fmaxf(mx1, __shfl_xor_sync(0xffffffffu, mx1, o));
    }
    if (g == 0) { red[w*8 + 2*t] = mx0; red[w*8 + 2*t+1] = mx1; }
    __syncthreads();
    float fm0 = -3e38f, fm1 = -3e38f;
#pragma unroll
    for (int ww = 0; ww < 8; ww++) {
        fm0 = fmaxf(fm0, red[ww*8 + 2*t]); fm1 = fmaxf(fm1, red[ww*8 + 2*t+1]);
    }
    float s0 = 0.f, s1 = 0.f;
#pragma unroll
    for (int i = 0; i < 16; i++) {
        float e = __expf(sc[i] - ((i & 1) ? fm1 : fm0));
        sc[i] = e;
        if (i & 1) s1 += e; else s0 += e;
    }
#pragma unroll
    for (int o = 4; o < 32; o <<= 1) {
        s0 += __shfl_xor_sync(0xffffffffu, s0, o);
        s1 += __shfl_xor_sync(0xffffffffu, s1, o);
    }
    if (g == 0) { red[64 + w*8 + 2*t] = s0; red[64 + w*8 + 2*t+1] = s1; }
    __syncthreads();
    float ts0 = 0.f, ts1 = 0.f;
#pragma unroll
    for (int ww = 0; ww < 8; ww++) { ts0 += red[64 + ww*8 + 2*t]; ts1 += red[64 + ww*8 + 2*t+1]; }
    float r0i = 1.f / ts0, r1i = 1.f / ts1;

    // stage probs [h][k] into relb (free now), then contiguous float4 store
    float* pbuf = relb;
    __syncthreads();
#pragma unroll
    for (int ch = 0; ch < 4; ch++) {
        int k0 = ch * 128 + w * 16;
#pragma unroll
        for (int j = 0; j < 4; j++) {
            int k = k0 + g + ((j >= 2) ? 8 : 0);
            int h = 2 * t + (j & 1);
            pbuf[h * NS + k] = sc[ch*4+j] * ((j & 1) ? r1i : r0i);
        }
    }
    __syncthreads();
    float* pout = &g_p[(size_t)(b*NS + q) * NH * NS];
    for (int i = tid; i < 1024; i += 256)
        *(float4*)&pout[i * 4] = *(const float4*)&pbuf[i * 4];
}

// ========= K5: out = probs @ v per (b,h), 2-stage single-sync ===============
__global__ void __launch_bounds__(256) k_pv(float* __restrict__ OUT) {
    const int bh = blockIdx.z, b = bh >> 3, h = bh & 7;
    const float* __restrict__ VT = &g_v[(size_t)bh * NDH * NS];
    __shared__ float As[2][64 * 36], Bs[2][64 * 36];
    const int tid = threadIdx.x, lane = tid & 31, w = tid >> 5;
    const int g = lane >> 2, t = lane & 3, wm = w >> 2, wn = w & 3;
    const int m0 = blockIdx.x * 64;
    const int lr = tid >> 3, lc = (tid & 7) * 4;
    float acc[2][2][4] = {};

    auto issue = [&](int ki) {
        int bi = ki & 1, kt = ki * 32;
#pragma unroll
        for (int rr = 0; rr < 2; rr++) {
            int r = lr + rr * 32;
            cpa16(&As[bi][r * 36 + lc], &g_p[((size_t)(b*NS + m0 + r)*NH + h)*NS + kt + lc]);
            cpa16(&Bs[bi][r * 36 + lc], &VT[(size_t)r * NS + kt + lc]);
        }
    };
    issue(0); CP_COMMIT();
    for (int ki = 0; ki < 16; ki++) {
        CP_WAIT0();
        __syncthreads();
        if (ki < 15) { issue(ki + 1); CP_COMMIT(); }
        const float* Af = As[ki & 1];
        const float* Bf = Bs[ki & 1];
#pragma unroll
        for (int ks = 0; ks < 4; ks++) {
            uint32_t a[2][4], bb[2][2];
#pragma unroll
            for (int mi = 0; mi < 2; mi++) {
                int r = wm * 32 + mi * 16 + g;
                a[mi][0] = f2tf(Af[r*36 + ks*8 + t]);     a[mi][1] = f2tf(Af[(r+8)*36 + ks*8 + t]);
                a[mi][2] = f2tf(Af[r*36 + ks*8 + t + 4]); a[mi][3] = f2tf(Af[(r+8)*36 + ks*8 + t + 4]);
            }
#pragma unroll
            for (int ni = 0; ni < 2; ni++) {
                int c = wn * 16 + ni * 8 + g;
                bb[ni][0] = f2tf(Bf[c*36 + ks*8 + t]); bb[ni][1] = f2tf(Bf[c*36 + ks*8 + t + 4]);
            }
#pragma unroll
            for (int mi = 0; mi < 2; mi++)
#pragma unroll
                for (int ni = 0; ni < 2; ni++) mma8(acc[mi][ni], a[mi], bb[ni]);
        }
    }
#pragma unroll
    for (int mi = 0; mi < 2; mi++)
#pragma unroll
        for (int ni = 0; ni < 2; ni++) {
            int m = m0 + wm*32 + mi*16 + g, n = wn*16 + ni*8 + 2*t;
            float* o1 = &OUT[(size_t)(b*NS + m)    *NDM + h*NDH + n];
            float* o2 = &OUT[(size_t)(b*NS + m + 8)*NDM + h*NDH + n];
            o1[0]=acc[mi][ni][0]; o1[1]=acc[mi][ni][1];
            o2[0]=acc[mi][ni][2]; o2[1]=acc[mi][ni][3];
        }
}

extern "C" void kernel_launch(void* const* d_in, const int* in_sizes, int n_in,
                              void* d_out, int out_size) {
    const float* X     = (const float*)d_in[0];
    const int*   GRAPH = (const int*)  d_in[1];
    const float* REL   = (const float*)d_in[2];
    const float* Wq    = (const float*)d_in[3];
    const float* Wk    = (const float*)d_in[4];
    const float* Wv    = (const float*)d_in[5];
    const float* Wr    = (const float*)d_in[6];
    const float* br    = (const float*)d_in[7];
    float* OUT = (float*)d_out;

    static bool attr_set = false;
    if (!attr_set) {
        cudaFuncSetAttribute(k_qkv,   cudaFuncAttributeMaxDynamicSharedMemorySize, K1_SMEM);
        cudaFuncSetAttribute(k_relsm, cudaFuncAttributeMaxDynamicSharedMemorySize, K4_SMEM);
        attr_set = true;
    }

    k_qkv  <<<dim3(32, 8, 3), 256, K1_SMEM>>>(X, Wq, Wk, Wv, Wr, br);
    k_qk   <<<dim3(8, 8, 32), 256>>>();
    k_relsm<<<dim3(512, 4), 256, K4_SMEM>>>(REL, GRAPH);
    k_pv   <<<dim3(8, 1, 32), 256>>>(OUT);
}